// round 2
// baseline (speedup 1.0000x reference)
#include <cuda_runtime.h>
#include <math.h>

#define BB 256
#define HH 512
#define CC 512
#define NL 128
#define TT 23
#define LSEQ 24
#define VV 64
#define BH (BB*HH)

typedef unsigned long long u64;

__device__ __forceinline__ void FMA2(u64 &d, u64 a, u64 b){
  asm("fma.rn.f32x2 %0, %1, %2, %0;" : "+l"(d) : "l"(a), "l"(b));
}
__device__ __forceinline__ u64 PACK2(float x, float y){
  u64 r; asm("mov.b64 %0, {%1, %2};" : "=l"(r) : "f"(x), "f"(y)); return r;
}
__device__ __forceinline__ float2 UNPK(u64 v){
  float2 r; asm("mov.b64 {%0, %1}, %2;" : "=f"(r.x), "=f"(r.y) : "l"(v)); return r;
}

// ---------------- static scratch ----------------
__device__ float g_Ws[(size_t)BB*NL*HH];       // 64 MB
__device__ float g_xg[(size_t)TT*BB*3*HH];     // 36 MB: precomputed x-part GRU0 gates
__device__ float g_xs[(size_t)TT*BH];
__device__ float g_ys[(size_t)TT*BH];
__device__ float g_y0[BH];
__device__ float g_h0buf[2][BH];
__device__ float g_h1buf[2][BH];
__device__ float g_nll[TT*BB];
__device__ float g_msk[TT*BB];

// ---------------- init hidden states ----------------
__global__ void k_inith(const float* __restrict__ init_state,
                        float* __restrict__ h0, float* __restrict__ h1){
  int idx = blockIdx.x*blockDim.x + threadIdx.x;
  if (idx < BH){
    int j = idx & (HH-1);
    h0[idx] = init_state[j];
    h1[idx] = init_state[HH + j];
  }
}

// ---------------- embedding gather ----------------
__global__ void k_embed(const float* __restrict__ emb, const int* __restrict__ seq,
                        float* __restrict__ xs){
  int idx = blockIdx.x*blockDim.x + threadIdx.x;
  if (idx < TT*BH){
    int h = idx & (HH-1);
    int r = idx >> 9;
    int b = r & (BB-1);
    int t = r >> 8;
    int tok = seq[b*LSEQ + t];
    xs[idx] = emb[(size_t)tok*HH + h];
  }
}

// ---------------- Ws GEMM (A = enc transposed layout), double-buffered f32x2 ----------------
// M=32768, N=512, K=512; 64x64 tiles, 4x4/thread, 256 thr
__global__ void __launch_bounds__(256) k_ws(const float* __restrict__ enc,
                                            const float* __restrict__ Ww,
                                            const float* __restrict__ Wb,
                                            float* __restrict__ Ws){
  __shared__ __align__(16) float At[2][16][68];
  __shared__ __align__(16) float Wt[2][16][68];
  int m0 = blockIdx.x*64, n0 = blockIdx.y*64;
  int b = m0 >> 7, l0 = m0 & 127;
  int tid = threadIdx.x, tm = tid & 15, tn = tid >> 4;
  u64 acc[4][2] = {};
  float2 ra[2], rw[2];

  auto loadT = [&](int t){
    int kc = t*16;
    #pragma unroll
    for (int i=0;i<2;i++){
      int kk = (tid>>5) + i*8, mm = (tid&31)*2;
      ra[i] = *(const float2*)&enc[(size_t)b*(CC*NL) + (size_t)(kc+kk)*NL + l0 + mm];
      int nn = (tid>>3) + i*32, kw = (tid&7)*2;
      rw[i] = *(const float2*)&Ww[(size_t)(n0+nn)*CC + kc + kw];
    }
  };
  auto storeT = [&](int buf){
    #pragma unroll
    for (int i=0;i<2;i++){
      int kk = (tid>>5) + i*8, mm = (tid&31)*2;
      *(float2*)&At[buf][kk][mm] = ra[i];
      int nn = (tid>>3) + i*32, kw = (tid&7)*2;
      Wt[buf][kw][nn] = rw[i].x; Wt[buf][kw+1][nn] = rw[i].y;
    }
  };

  loadT(0); storeT(0); __syncthreads();
  for (int t=0;t<32;t++){
    int buf = t & 1;
    if (t+1 < 32) loadT(t+1);
    #pragma unroll
    for (int kk=0;kk<16;kk++){
      float4 av = *(const float4*)&At[buf][kk][tm*4];
      ulonglong2 wv = *(const ulonglong2*)&Wt[buf][kk][tn*4];
      u64 a0=PACK2(av.x,av.x), a1=PACK2(av.y,av.y), a2=PACK2(av.z,av.z), a3=PACK2(av.w,av.w);
      FMA2(acc[0][0],a0,wv.x); FMA2(acc[0][1],a0,wv.y);
      FMA2(acc[1][0],a1,wv.x); FMA2(acc[1][1],a1,wv.y);
      FMA2(acc[2][0],a2,wv.x); FMA2(acc[2][1],a2,wv.y);
      FMA2(acc[3][0],a3,wv.x); FMA2(acc[3][1],a3,wv.y);
    }
    if (t+1 < 32) storeT((t+1)&1);
    __syncthreads();
  }
  #pragma unroll
  for (int mi=0;mi<4;mi++){
    int m = m0 + tm*4 + mi;
    #pragma unroll
    for (int h=0;h<2;h++){
      float2 p = UNPK(acc[mi][h]);
      int n = n0 + tn*4 + h*2;
      Ws[(size_t)m*HH + n]   = p.x + Wb[n];
      Ws[(size_t)m*HH + n+1] = p.y + Wb[n+1];
    }
  }
}

// ---------------- big GEMM: C[M,N] = A[M,512] @ Wrows^T (row stride wS, col off wOff) ------
// 64x64 tiles, 4x4/thread. Used for xg precompute (M=5888, N=1536).
__global__ void __launch_bounds__(256) k_gemmT(const float* __restrict__ A,
                                               const float* __restrict__ W,
                                               int wS, int wOff,
                                               float* __restrict__ C, int ldc){
  __shared__ __align__(16) float At[2][16][68];
  __shared__ __align__(16) float Wt[2][16][68];
  int m0 = blockIdx.x*64, n0 = blockIdx.y*64;
  int tid = threadIdx.x, tm = tid & 15, tn = tid >> 4;
  u64 acc[4][2] = {};
  float2 ra[2], rw[2];

  auto loadT = [&](int t){
    int kc = t*16;
    #pragma unroll
    for (int i=0;i<2;i++){
      int mm = (tid>>3) + i*32, kk = (tid&7)*2;
      ra[i] = *(const float2*)&A[(size_t)(m0+mm)*512 + kc + kk];
      rw[i] = *(const float2*)&W[(size_t)(n0+mm)*wS + wOff + kc + kk];
    }
  };
  auto storeT = [&](int buf){
    #pragma unroll
    for (int i=0;i<2;i++){
      int mm = (tid>>3) + i*32, kk = (tid&7)*2;
      At[buf][kk][mm] = ra[i].x; At[buf][kk+1][mm] = ra[i].y;
      Wt[buf][kk][mm] = rw[i].x; Wt[buf][kk+1][mm] = rw[i].y;
    }
  };

  loadT(0); storeT(0); __syncthreads();
  for (int t=0;t<32;t++){
    int buf = t & 1;
    if (t+1 < 32) loadT(t+1);
    #pragma unroll
    for (int kk=0;kk<16;kk++){
      float4 av = *(const float4*)&At[buf][kk][tm*4];
      ulonglong2 wv = *(const ulonglong2*)&Wt[buf][kk][tn*4];
      u64 a0=PACK2(av.x,av.x), a1=PACK2(av.y,av.y), a2=PACK2(av.z,av.z), a3=PACK2(av.w,av.w);
      FMA2(acc[0][0],a0,wv.x); FMA2(acc[0][1],a0,wv.y);
      FMA2(acc[1][0],a1,wv.x); FMA2(acc[1][1],a1,wv.y);
      FMA2(acc[2][0],a2,wv.x); FMA2(acc[2][1],a2,wv.y);
      FMA2(acc[3][0],a3,wv.x); FMA2(acc[3][1],a3,wv.y);
    }
    if (t+1 < 32) storeT((t+1)&1);
    __syncthreads();
  }
  #pragma unroll
  for (int mi=0;mi<4;mi++){
    int m = m0 + tm*4 + mi;
    #pragma unroll
    for (int h=0;h<2;h++){
      float2 p = UNPK(acc[mi][h]);
      int n = n0 + tn*4 + h*2;
      C[(size_t)m*ldc + n]   = p.x;
      C[(size_t)m*ldc + n+1] = p.y;
    }
  }
}

// ---------------- fused GRU: both gate GEMMs + pointwise, double-buffered f32x2 -----------
// 32b x 32j tile, 256 thr, 2x2/thread per gate set. Optional precomputed xg addend.
#define GRU_INNER(N0, N1)                                              \
  _Pragma("unroll")                                                    \
  for (int kk=0;kk<16;kk++){                                           \
    float2 a = *(const float2*)&At[buf][kk][tb*2];                     \
    u64 ax = PACK2(a.x,a.x), ay = PACK2(a.y,a.y);                      \
    u64 wr = *(const u64*)&Wt[buf][0][kk][tj*2];                       \
    u64 wz = *(const u64*)&Wt[buf][1][kk][tj*2];                       \
    u64 wn = *(const u64*)&Wt[buf][2][kk][tj*2];                       \
    FMA2(ar0,ax,wr); FMA2(ar1,ay,wr);                                  \
    FMA2(az0,ax,wz); FMA2(az1,ay,wz);                                  \
    FMA2(N0,ax,wn);  FMA2(N1,ay,wn);                                   \
  }

__global__ void __launch_bounds__(256) k_gru(const float* __restrict__ srcA,
                                             const float* __restrict__ xg,
                                             const float* __restrict__ hprev,
                                             const float* __restrict__ wih, int wihS,
                                             const float* __restrict__ whh,
                                             const float* __restrict__ bih,
                                             const float* __restrict__ bhh,
                                             float* __restrict__ hnew){
  __shared__ __align__(16) float At[2][16][34];
  __shared__ __align__(16) float Wt[2][3][16][34];
  int b0 = blockIdx.x*32, j0 = blockIdx.y*32;
  int tid = threadIdx.x, tb = tid & 15, tj = tid >> 4;
  u64 ar0=0,ar1=0,az0=0,az1=0,ani0=0,ani1=0,anh0=0,anh1=0;
  const int bb = tid>>3, kA = (tid&7)*2;
  float2 ra; float2 rw[3];

  auto loadT = [&](int t){
    int ph = t >> 5; int kc = (t & 31)*16;
    const float* As = ph ? hprev : srcA;
    ra = *(const float2*)&As[(size_t)(b0+bb)*HH + kc + kA];
    #pragma unroll
    for (int i=0;i<3;i++){
      int r = (tid>>3) + i*32;
      int g = r >> 5, jj = r & 31;
      const float* Wsrc = ph ? (whh + (size_t)(g*HH + j0 + jj)*HH)
                             : (wih + (size_t)(g*HH + j0 + jj)*wihS);
      rw[i] = *(const float2*)&Wsrc[kc + kA];
    }
  };
  auto storeT = [&](int buf){
    At[buf][kA][bb] = ra.x; At[buf][kA+1][bb] = ra.y;
    #pragma unroll
    for (int i=0;i<3;i++){
      int r = (tid>>3) + i*32;
      int g = r >> 5, jj = r & 31;
      Wt[buf][g][kA][jj] = rw[i].x; Wt[buf][g][kA+1][jj] = rw[i].y;
    }
  };

  loadT(0); storeT(0); __syncthreads();
  for (int t=0;t<64;t++){
    int buf = t & 1;
    if (t+1 < 64) loadT(t+1);
    if (t < 32) { GRU_INNER(ani0, ani1) }
    else        { GRU_INNER(anh0, anh1) }
    if (t+1 < 64) storeT((t+1)&1);
    __syncthreads();
  }

  float2 vr[2] = {UNPK(ar0), UNPK(ar1)};
  float2 vz[2] = {UNPK(az0), UNPK(az1)};
  float2 vi[2] = {UNPK(ani0), UNPK(ani1)};
  float2 vh[2] = {UNPK(anh0), UNPK(anh1)};
  #pragma unroll
  for (int bi=0;bi<2;bi++){
    int b = b0 + tb*2 + bi;
    float Ar[2] = {vr[bi].x, vr[bi].y};
    float Az[2] = {vz[bi].x, vz[bi].y};
    float Ai[2] = {vi[bi].x, vi[bi].y};
    float Ah[2] = {vh[bi].x, vh[bi].y};
    #pragma unroll
    for (int ji=0;ji<2;ji++){
      int j = j0 + tj*2 + ji;
      float gr = Ar[ji] + bih[j]      + bhh[j];
      float gz = Az[ji] + bih[HH+j]   + bhh[HH+j];
      float gi = Ai[ji] + bih[2*HH+j];
      float gh = Ah[ji] + bhh[2*HH+j];
      if (xg){
        const float* xr = xg + (size_t)b*(3*HH);
        gr += xr[j]; gz += xr[HH+j]; gi += xr[2*HH+j];
      }
      float r = 1.f/(1.f+expf(-gr));
      float z = 1.f/(1.f+expf(-gz));
      float n = tanhf(gi + r*gh);
      float hp = hprev[(size_t)b*HH + j];
      hnew[(size_t)b*HH + j] = (1.f-z)*n + z*hp;
    }
  }
}

// ---------------- fused Uh + attention + fc: one block per batch row ----------------
__global__ void __launch_bounds__(256) k_attnfc(const float* __restrict__ Ws,
                                                const float* __restrict__ enc,
                                                const float* __restrict__ h1,
                                                const float* __restrict__ aU,
                                                const float* __restrict__ aUb,
                                                const float* __restrict__ vw,
                                                const float* __restrict__ vb,
                                                const float* __restrict__ fcw,
                                                const float* __restrict__ fcb,
                                                float* __restrict__ yout){
  __shared__ __align__(16) float hs[HH];
  __shared__ __align__(16) float us[HH];
  __shared__ __align__(16) float vs[HH];
  __shared__ __align__(16) float cx[HH];
  __shared__ __align__(16) float sc[NL];
  int b = blockIdx.x, tid = threadIdx.x;
  int warp = tid >> 5, lane = tid & 31;

  *(float2*)&hs[tid*2] = *(const float2*)&h1[(size_t)b*HH + tid*2];
  *(float2*)&vs[tid*2] = *(const float2*)&vw[tid*2];
  __syncthreads();

  // u = aU @ h + aUb  (2 rows per thread)
  #pragma unroll
  for (int jj=0;jj<2;jj++){
    int j = tid + jj*256;
    const ulonglong2* wr = (const ulonglong2*)(aU + (size_t)j*HH);
    u64 a0=0,a1=0,a2=0,a3=0;
    #pragma unroll 2
    for (int i=0;i<128;i+=2){
      ulonglong2 w0 = wr[i], w1 = wr[i+1];
      ulonglong2 h0 = *(const ulonglong2*)&hs[i*4];
      ulonglong2 h1v = *(const ulonglong2*)&hs[i*4+4];
      FMA2(a0,w0.x,h0.x); FMA2(a1,w0.y,h0.y);
      FMA2(a2,w1.x,h1v.x); FMA2(a3,w1.y,h1v.y);
    }
    float2 p0=UNPK(a0), p1=UNPK(a1), p2=UNPK(a2), p3=UNPK(a3);
    us[j] = aUb[j] + (((p0.x+p0.y)+(p1.x+p1.y)) + ((p2.x+p2.y)+(p3.x+p3.y)));
  }
  __syncthreads();

  float vb0 = vb[0];
  // scores[l] = sum_h relu(Ws + u) * v + vb
  for (int l = warp; l < NL; l += 8){
    const float4* wr = (const float4*)(Ws + ((size_t)b*NL + l)*HH);
    float s = 0.f;
    #pragma unroll
    for (int q=0;q<4;q++){
      int i4 = lane + q*32;
      float4 w = wr[i4];
      float4 u4 = *(const float4*)&us[i4*4];
      float4 v4 = *(const float4*)&vs[i4*4];
      s += fmaxf(w.x+u4.x,0.f)*v4.x + fmaxf(w.y+u4.y,0.f)*v4.y
         + fmaxf(w.z+u4.z,0.f)*v4.z + fmaxf(w.w+u4.w,0.f)*v4.w;
    }
    #pragma unroll
    for (int o=16;o;o>>=1) s += __shfl_xor_sync(0xffffffffu,s,o);
    if (!lane) sc[l] = s + vb0;
  }
  __syncthreads();
  // softmax (warp 0)
  if (tid < 32){
    float m = -1e30f;
    for (int l = tid; l < NL; l += 32) m = fmaxf(m, sc[l]);
    #pragma unroll
    for (int o=16;o;o>>=1) m = fmaxf(m, __shfl_xor_sync(0xffffffffu,m,o));
    float s = 0.f;
    for (int l = tid; l < NL; l += 32){ float e = expf(sc[l]-m); sc[l] = e; s += e; }
    #pragma unroll
    for (int o=16;o;o>>=1) s += __shfl_xor_sync(0xffffffffu,s,o);
    float inv = 1.f/s;
    for (int l = tid; l < NL; l += 32) sc[l] *= inv;
  }
  __syncthreads();
  // ctx[c] = sum_l a[l] * enc[b,c,l]
  float4 av4 = *(const float4*)&sc[lane*4];
  for (int c = warp; c < CC; c += 8){
    float4 e = *(const float4*)&enc[((size_t)b*CC + c)*NL + lane*4];
    float s = e.x*av4.x + e.y*av4.y + e.z*av4.z + e.w*av4.w;
    #pragma unroll
    for (int o=16;o;o>>=1) s += __shfl_xor_sync(0xffffffffu,s,o);
    if (!lane) cx[c] = s;
  }
  __syncthreads();
  // y = relu(fcw @ [ctx, h] + fcb)  (2 rows per thread)
  #pragma unroll
  for (int jj=0;jj<2;jj++){
    int j = tid + jj*256;
    const ulonglong2* wr = (const ulonglong2*)(fcw + (size_t)j*(CC+HH));
    u64 a0=0,a1=0,a2=0,a3=0;
    #pragma unroll 2
    for (int i=0;i<128;i+=2){
      ulonglong2 w0 = wr[i], w1 = wr[i+1];
      ulonglong2 c0 = *(const ulonglong2*)&cx[i*4];
      ulonglong2 c1 = *(const ulonglong2*)&cx[i*4+4];
      FMA2(a0,w0.x,c0.x); FMA2(a1,w0.y,c0.y);
      FMA2(a2,w1.x,c1.x); FMA2(a3,w1.y,c1.y);
    }
    #pragma unroll 2
    for (int i=0;i<128;i+=2){
      ulonglong2 w0 = wr[128+i], w1 = wr[128+i+1];
      ulonglong2 h0 = *(const ulonglong2*)&hs[i*4];
      ulonglong2 h1v = *(const ulonglong2*)&hs[i*4+4];
      FMA2(a0,w0.x,h0.x); FMA2(a1,w0.y,h0.y);
      FMA2(a2,w1.x,h1v.x); FMA2(a3,w1.y,h1v.y);
    }
    float2 p0=UNPK(a0), p1=UNPK(a1), p2=UNPK(a2), p3=UNPK(a3);
    float y = (((p0.x+p0.y)+(p1.x+p1.y)) + ((p2.x+p2.y)+(p3.x+p3.y))) + fcb[j];
    yout[(size_t)b*HH + j] = fmaxf(y, 0.f);
  }
}

// ---------------- logits + per-token masked NLL ----------------
__global__ void __launch_bounds__(128) k_logits(const float* __restrict__ ys,
                                                const float* __restrict__ clsw,
                                                const float* __restrict__ clsb,
                                                const int* __restrict__ seq,
                                                float* __restrict__ nll,
                                                float* __restrict__ msk){
  __shared__ float yb[HH];
  __shared__ float lg[VV];
  int t = blockIdx.x >> 8;
  int b = blockIdx.x & 255;
  int tid = threadIdx.x;
  for (int i = tid; i < HH; i += 128)
    yb[i] = ys[((size_t)t*BB + b)*HH + i];
  __syncthreads();
  {
    int v = tid >> 1, half = tid & 1;
    const float4* wr = (const float4*)(clsw + (size_t)v*HH + half*256);
    const float4* yr = (const float4*)(yb + half*256);
    float s = 0.f;
    #pragma unroll 8
    for (int i = 0; i < 64; i++){
      float4 w = wr[i], y = yr[i];
      s += w.x*y.x + w.y*y.y + w.z*y.z + w.w*y.w;
    }
    s += __shfl_xor_sync(0xffffffffu, s, 1);
    if (!half) lg[v] = s + clsb[v];
  }
  __syncthreads();
  if (tid == 0){
    float m = lg[0];
    #pragma unroll
    for (int v = 1; v < VV; v++) m = fmaxf(m, lg[v]);
    float se = 0.f;
    #pragma unroll
    for (int v = 0; v < VV; v++) se += expf(lg[v]-m);
    int label = seq[b*LSEQ + t + 1];
    float lp = lg[label] - m - logf(se);
    bool mk = label > 0;
    nll[blockIdx.x] = mk ? -lp : 0.f;
    msk[blockIdx.x] = mk ? 1.f : 0.f;
  }
}

// ---------------- deterministic final reduction ----------------
__global__ void __launch_bounds__(256) k_reduce(const float* __restrict__ nll,
                                                const float* __restrict__ msk,
                                                float* __restrict__ out){
  __shared__ float sn[256], sm[256];
  int tid = threadIdx.x;
  float a = 0.f, c = 0.f;
  for (int i = tid; i < TT*BB; i += 256){ a += nll[i]; c += msk[i]; }
  sn[tid] = a; sm[tid] = c;
  __syncthreads();
  for (int o = 128; o; o >>= 1){
    if (tid < o){ sn[tid] += sn[tid+o]; sm[tid] += sm[tid+o]; }
    __syncthreads();
  }
  if (tid == 0) out[0] = sn[0] / sm[0];
}

// ---------------- host orchestration ----------------
extern "C" void kernel_launch(void* const* d_in, const int* in_sizes, int n_in,
                              void* d_out, int out_size){
  (void)in_sizes; (void)n_in; (void)out_size;
  const float* enc   = (const float*)d_in[0];
  const int*   seq   = (const int*)  d_in[1];
  const float* emb   = (const float*)d_in[3];
  const float* inis  = (const float*)d_in[4];
  const float* aWw   = (const float*)d_in[5];
  const float* aWb   = (const float*)d_in[6];
  const float* aUw   = (const float*)d_in[7];
  const float* aUb   = (const float*)d_in[8];
  const float* avw   = (const float*)d_in[9];
  const float* avb   = (const float*)d_in[10];
  const float* fcw   = (const float*)d_in[11];
  const float* fcb   = (const float*)d_in[12];
  const float* clsw  = (const float*)d_in[13];
  const float* clsb  = (const float*)d_in[14];
  const float* g0wih = (const float*)d_in[15];
  const float* g0whh = (const float*)d_in[16];
  const float* g0bih = (const float*)d_in[17];
  const float* g0bhh = (const float*)d_in[18];
  const float* g1wih = (const float*)d_in[19];
  const float* g1whh = (const float*)d_in[20];
  const float* g1bih = (const float*)d_in[21];
  const float* g1bhh = (const float*)d_in[22];

  float *Ws, *xg, *xs, *ys, *y0, *h0b, *h1b, *nll, *msk;
  cudaGetSymbolAddress((void**)&Ws,  g_Ws);
  cudaGetSymbolAddress((void**)&xg,  g_xg);
  cudaGetSymbolAddress((void**)&xs,  g_xs);
  cudaGetSymbolAddress((void**)&ys,  g_ys);
  cudaGetSymbolAddress((void**)&y0,  g_y0);
  cudaGetSymbolAddress((void**)&h0b, g_h0buf);
  cudaGetSymbolAddress((void**)&h1b, g_h1buf);
  cudaGetSymbolAddress((void**)&nll, g_nll);
  cudaGetSymbolAddress((void**)&msk, g_msk);

  // precompute (parallel, one-shot)
  k_inith<<<(BH+255)/256, 256>>>(inis, h0b, h1b);
  k_embed<<<(TT*BH+255)/256, 256>>>(emb, seq, xs);
  k_ws<<<dim3(512, 8), 256>>>(enc, aWw, aWb, Ws);
  // xg[t*B+b, 3H] = x_t[b] @ wih[:, 512:1024]^T   (y occupies cols 0..511)
  k_gemmT<<<dim3(92, 24), 256>>>(xs, g0wih, 1024, 512, xg, 3*HH);

  // y0
  k_attnfc<<<BB, 256>>>(Ws, enc, h1b, aUw, aUb, avw, avb, fcw, fcb, y0);

  const float* yprev = y0;
  for (int t = 0; t < TT; t++){
    float* h0r = h0b + (size_t)(t & 1)*BH;
    float* h0w = h0b + (size_t)((t+1) & 1)*BH;
    float* h1r = h1b + (size_t)(t & 1)*BH;
    float* h1w = h1b + (size_t)((t+1) & 1)*BH;
    k_gru<<<dim3(8,16), 256>>>(yprev, xg + (size_t)t*BB*3*HH, h0r,
                               g0wih, 1024, g0whh, g0bih, g0bhh, h0w);
    k_gru<<<dim3(8,16), 256>>>(h0w, (const float*)nullptr, h1r,
                               g1wih, 512, g1whh, g1bih, g1bhh, h1w);
    k_attnfc<<<BB, 256>>>(Ws, enc, h1w, aUw, aUb, avw, avb, fcw, fcb,
                          ys + (size_t)t*BH);
    yprev = ys + (size_t)t*BH;
  }

  k_logits<<<TT*BB, 128>>>(ys, clsw, clsb, seq, nll, msk);
  k_reduce<<<1, 256>>>(nll, msk, (float*)d_out);
}

// round 3
// speedup vs baseline: 1.0462x; 1.0462x over previous
#include <cuda_runtime.h>
#include <cuda_bf16.h>
#include <math.h>

#define BB 256
#define HH 512
#define CC 512
#define NL 128
#define TT 23
#define LSEQ 24
#define VV 64
#define BH (BB*HH)

typedef unsigned long long u64;

__device__ __forceinline__ void FMA2(u64 &d, u64 a, u64 b){
  asm("fma.rn.f32x2 %0, %1, %2, %0;" : "+l"(d) : "l"(a), "l"(b));
}
__device__ __forceinline__ u64 PACK2(float x, float y){
  u64 r; asm("mov.b64 %0, {%1, %2};" : "=l"(r) : "f"(x), "f"(y)); return r;
}
__device__ __forceinline__ float2 UNPK(u64 v){
  float2 r; asm("mov.b64 {%0, %1}, %2;" : "=f"(r.x), "=f"(r.y) : "l"(v)); return r;
}

// ---------------- static scratch ----------------
__device__ __nv_bfloat16 g_Wsh[(size_t)BB*NL*HH];   // 33.5 MB bf16 Ws
__device__ __nv_bfloat16 g_ench[(size_t)BB*CC*NL];  // 33.5 MB bf16 enc
__device__ float g_xg[(size_t)TT*BB*3*HH];          // precomputed x-part GRU0 gates
__device__ float g_xs[(size_t)TT*BH];
__device__ float g_ys[(size_t)TT*BH];
__device__ float g_y0[BH];
__device__ float g_h0buf[2][BH];
__device__ float g_h1buf[2][BH];
__device__ float g_gates[(size_t)BB*3*HH];
__device__ float g_gatesH[(size_t)BB*HH];
__device__ float g_nll[TT*BB];
__device__ float g_msk[TT*BB];

// ---------------- init hidden states ----------------
__global__ void k_inith(const float* __restrict__ init_state,
                        float* __restrict__ h0, float* __restrict__ h1){
  int idx = blockIdx.x*blockDim.x + threadIdx.x;
  if (idx < BH){
    int j = idx & (HH-1);
    h0[idx] = init_state[j];
    h1[idx] = init_state[HH + j];
  }
}

// ---------------- embedding gather ----------------
__global__ void k_embed(const float* __restrict__ emb, const int* __restrict__ seq,
                        float* __restrict__ xs){
  int idx = blockIdx.x*blockDim.x + threadIdx.x;
  if (idx < TT*BH){
    int h = idx & (HH-1);
    int r = idx >> 9;
    int b = r & (BB-1);
    int t = r >> 8;
    int tok = seq[b*LSEQ + t];
    xs[idx] = emb[(size_t)tok*HH + h];
  }
}

// ---------------- fp32 -> bf16 copy ----------------
__global__ void k_tobf16(const float* __restrict__ in, __nv_bfloat16* __restrict__ out, int n4){
  int idx = blockIdx.x*blockDim.x + threadIdx.x;
  if (idx < n4){
    float4 v = *(const float4*)&in[(size_t)idx*4];
    *(__nv_bfloat162*)&out[(size_t)idx*4]   = __floats2bfloat162_rn(v.x, v.y);
    *(__nv_bfloat162*)&out[(size_t)idx*4+2] = __floats2bfloat162_rn(v.z, v.w);
  }
}

// ---------------- Ws GEMM -> bf16 out. M=32768, N=512, K=512 ----------------
__global__ void __launch_bounds__(256) k_ws(const float* __restrict__ enc,
                                            const float* __restrict__ Ww,
                                            const float* __restrict__ Wb,
                                            __nv_bfloat16* __restrict__ Wsh){
  __shared__ __align__(16) float At[2][16][68];
  __shared__ __align__(16) float Wt[2][16][68];
  int m0 = blockIdx.x*64, n0 = blockIdx.y*64;
  int bb_ = m0 >> 7, l0 = m0 & 127;
  int tid = threadIdx.x, tm = tid & 15, tn = tid >> 4;
  u64 acc[4][2] = {};
  float4 raA, raW;
  int akk = tid >> 4, al4 = (tid & 15)*4;
  int wnn = tid >> 2, wk4 = (tid & 3)*4;

  auto loadT = [&](int t){
    int kc = t*16;
    raA = *(const float4*)&enc[(size_t)bb_*CC*NL + (size_t)(kc + akk)*NL + l0 + al4];
    raW = *(const float4*)&Ww[(size_t)(n0 + wnn)*CC + kc + wk4];
  };
  auto storeT = [&](int buf){
    *(float4*)&At[buf][akk][al4] = raA;
    Wt[buf][wk4+0][wnn]=raW.x; Wt[buf][wk4+1][wnn]=raW.y;
    Wt[buf][wk4+2][wnn]=raW.z; Wt[buf][wk4+3][wnn]=raW.w;
  };

  loadT(0); storeT(0); __syncthreads();
  for (int t=0;t<32;t++){
    int buf = t & 1;
    if (t+1 < 32) loadT(t+1);
    #pragma unroll
    for (int kk=0;kk<16;kk++){
      float4 av = *(const float4*)&At[buf][kk][tm*4];
      ulonglong2 wv = *(const ulonglong2*)&Wt[buf][kk][tn*4];
      u64 a0=PACK2(av.x,av.x), a1=PACK2(av.y,av.y), a2=PACK2(av.z,av.z), a3=PACK2(av.w,av.w);
      FMA2(acc[0][0],a0,wv.x); FMA2(acc[0][1],a0,wv.y);
      FMA2(acc[1][0],a1,wv.x); FMA2(acc[1][1],a1,wv.y);
      FMA2(acc[2][0],a2,wv.x); FMA2(acc[2][1],a2,wv.y);
      FMA2(acc[3][0],a3,wv.x); FMA2(acc[3][1],a3,wv.y);
    }
    if (t+1 < 32) storeT((t+1)&1);
    __syncthreads();
  }
  #pragma unroll
  for (int mi=0;mi<4;mi++){
    int m = m0 + tm*4 + mi;
    #pragma unroll
    for (int h=0;h<2;h++){
      float2 p = UNPK(acc[mi][h]);
      int n = n0 + tn*4 + h*2;
      *(__nv_bfloat162*)&Wsh[(size_t)m*HH + n] =
          __floats2bfloat162_rn(p.x + Wb[n], p.y + Wb[n+1]);
    }
  }
}

// ---------------- single-phase GEMM (xg precompute): C = A[M,512] @ W(stride,off)^T ----------
__global__ void __launch_bounds__(256) k_mm1(const float* __restrict__ A,
                                             const float* __restrict__ W,
                                             int ws, int wOff,
                                             float* __restrict__ C, int ldc){
  __shared__ __align__(16) float At[2][16][68];
  __shared__ __align__(16) float Wt[2][16][68];
  int m0 = blockIdx.x*64, n0 = blockIdx.y*64;
  int tid = threadIdx.x, tm = tid & 15, tn = tid >> 4;
  u64 acc[4][2] = {};
  float4 ra, rw;
  int mm = tid >> 2, k4 = (tid & 3)*4;

  auto loadT = [&](int t){
    int kc = t*16;
    ra = *(const float4*)&A[(size_t)(m0+mm)*512 + kc + k4];
    rw = *(const float4*)&W[(size_t)(n0+mm)*ws + wOff + kc + k4];
  };
  auto storeT = [&](int buf){
    At[buf][k4+0][mm]=ra.x; At[buf][k4+1][mm]=ra.y; At[buf][k4+2][mm]=ra.z; At[buf][k4+3][mm]=ra.w;
    Wt[buf][k4+0][mm]=rw.x; Wt[buf][k4+1][mm]=rw.y; Wt[buf][k4+2][mm]=rw.z; Wt[buf][k4+3][mm]=rw.w;
  };

  loadT(0); storeT(0); __syncthreads();
  for (int t=0;t<32;t++){
    int buf = t & 1;
    if (t+1 < 32) loadT(t+1);
    #pragma unroll
    for (int kk=0;kk<16;kk++){
      float4 av = *(const float4*)&At[buf][kk][tm*4];
      ulonglong2 wv = *(const ulonglong2*)&Wt[buf][kk][tn*4];
      u64 a0=PACK2(av.x,av.x), a1=PACK2(av.y,av.y), a2=PACK2(av.z,av.z), a3=PACK2(av.w,av.w);
      FMA2(acc[0][0],a0,wv.x); FMA2(acc[0][1],a0,wv.y);
      FMA2(acc[1][0],a1,wv.x); FMA2(acc[1][1],a1,wv.y);
      FMA2(acc[2][0],a2,wv.x); FMA2(acc[2][1],a2,wv.y);
      FMA2(acc[3][0],a3,wv.x); FMA2(acc[3][1],a3,wv.y);
    }
    if (t+1 < 32) storeT((t+1)&1);
    __syncthreads();
  }
  #pragma unroll
  for (int mi=0;mi<4;mi++){
    int m = m0 + tm*4 + mi;
    #pragma unroll
    for (int h=0;h<2;h++){
      float2 p = UNPK(acc[mi][h]);
      int n = n0 + tn*4 + h*2;
      *(float2*)&C[(size_t)m*ldc + n] = make_float2(p.x, p.y);
    }
  }
}

// ---------------- GRU gates GEMM: two K-phases, n-gate split ----------------
// gates[256,1536] = A0[256,512] @ W0(s0)^T  +  A1[256,512] @ W1(512)^T
// For n-gate columns (n>=1024), phase1 goes to gatesH[256,512] instead.
#define MM_INNER(ACC)                                                        \
  _Pragma("unroll")                                                          \
  for (int kk=0;kk<16;kk++){                                                 \
    float4 av = *(const float4*)&At[buf][kk][tm*4];                          \
    ulonglong2 wv = *(const ulonglong2*)&Wt[buf][kk][tn*4];                  \
    u64 a0=PACK2(av.x,av.x), a1=PACK2(av.y,av.y), a2=PACK2(av.z,av.z), a3=PACK2(av.w,av.w); \
    FMA2(ACC[0][0],a0,wv.x); FMA2(ACC[0][1],a0,wv.y);                        \
    FMA2(ACC[1][0],a1,wv.x); FMA2(ACC[1][1],a1,wv.y);                        \
    FMA2(ACC[2][0],a2,wv.x); FMA2(ACC[2][1],a2,wv.y);                        \
    FMA2(ACC[3][0],a3,wv.x); FMA2(ACC[3][1],a3,wv.y);                        \
  }

__global__ void __launch_bounds__(256) k_gates(const float* __restrict__ A0,
                                               const float* __restrict__ A1,
                                               const float* __restrict__ W0, int s0,
                                               const float* __restrict__ W1,
                                               float* __restrict__ gates,
                                               float* __restrict__ gatesH){
  __shared__ __align__(16) float At[2][16][68];
  __shared__ __align__(16) float Wt[2][16][68];
  int m0 = blockIdx.x*64, n0 = blockIdx.y*64;
  int tid = threadIdx.x, tm = tid & 15, tn = tid >> 4;
  bool nsplit = (n0 >= 2*HH);
  u64 acc[4][2] = {};
  u64 acc2[4][2] = {};
  float4 ra, rw;
  int mm = tid >> 2, k4 = (tid & 3)*4;

  auto loadT = [&](int t){
    int kc = (t & 31)*16;
    const float* A = (t < 32) ? A0 : A1;
    const float* W = (t < 32) ? W0 : W1;
    int ws = (t < 32) ? s0 : 512;
    ra = *(const float4*)&A[(size_t)(m0+mm)*512 + kc + k4];
    rw = *(const float4*)&W[(size_t)(n0+mm)*ws + kc + k4];
  };
  auto storeT = [&](int buf){
    At[buf][k4+0][mm]=ra.x; At[buf][k4+1][mm]=ra.y; At[buf][k4+2][mm]=ra.z; At[buf][k4+3][mm]=ra.w;
    Wt[buf][k4+0][mm]=rw.x; Wt[buf][k4+1][mm]=rw.y; Wt[buf][k4+2][mm]=rw.z; Wt[buf][k4+3][mm]=rw.w;
  };

  loadT(0); storeT(0); __syncthreads();
  for (int t=0;t<64;t++){
    int buf = t & 1;
    if (t+1 < 64) loadT(t+1);
    if (t >= 32 && nsplit) { MM_INNER(acc2) }
    else                   { MM_INNER(acc) }
    if (t+1 < 64) storeT((t+1)&1);
    __syncthreads();
  }
  #pragma unroll
  for (int mi=0;mi<4;mi++){
    int m = m0 + tm*4 + mi;
    #pragma unroll
    for (int h=0;h<2;h++){
      float2 p = UNPK(acc[mi][h]);
      int n = n0 + tn*4 + h*2;
      *(float2*)&gates[(size_t)m*(3*HH) + n] = make_float2(p.x, p.y);
      if (nsplit){
        float2 q = UNPK(acc2[mi][h]);
        *(float2*)&gatesH[(size_t)m*HH + (n - 2*HH)] = make_float2(q.x, q.y);
      }
    }
  }
}

// ---------------- GRU pointwise ----------------
__global__ void __launch_bounds__(256) k_pw(const float* __restrict__ gates,
                                            const float* __restrict__ gatesH,
                                            const float* __restrict__ xg,
                                            const float* __restrict__ hprev,
                                            const float* __restrict__ bih,
                                            const float* __restrict__ bhh,
                                            float* __restrict__ hnew){
  int idx = blockIdx.x*256 + threadIdx.x;   // < 131072
  int b = idx >> 9, j = idx & (HH-1);
  const float* g = gates + (size_t)b*(3*HH);
  float gr = g[j], gz = g[HH+j], gi = g[2*HH+j];
  if (xg){
    const float* x = xg + (size_t)b*(3*HH);
    gr += x[j]; gz += x[HH+j]; gi += x[2*HH+j];
  }
  gr += bih[j] + bhh[j];
  gz += bih[HH+j] + bhh[HH+j];
  gi += bih[2*HH+j];
  float gh = gatesH[(size_t)b*HH + j] + bhh[2*HH+j];
  float r = 1.f/(1.f+expf(-gr));
  float z = 1.f/(1.f+expf(-gz));
  float n = tanhf(gi + r*gh);
  hnew[idx] = (1.f-z)*n + z*hprev[idx];
}

// ---------------- fused Uh + attention + fc (bf16 streaming) ----------------
__global__ void __launch_bounds__(256) k_attnfc(const __nv_bfloat16* __restrict__ Wsh,
                                                const __nv_bfloat16* __restrict__ ench,
                                                const float* __restrict__ h1,
                                                const float* __restrict__ aU,
                                                const float* __restrict__ aUb,
                                                const float* __restrict__ vw,
                                                const float* __restrict__ vb,
                                                const float* __restrict__ fcw,
                                                const float* __restrict__ fcb,
                                                float* __restrict__ yout){
  __shared__ __align__(16) float hs[HH];
  __shared__ __align__(16) float us[HH];
  __shared__ __align__(16) float vs[HH];
  __shared__ __align__(16) float cx[HH];
  __shared__ __align__(16) float sc[NL];
  int b = blockIdx.x, tid = threadIdx.x;

  *(float2*)&hs[tid*2] = *(const float2*)&h1[(size_t)b*HH + tid*2];
  *(float2*)&vs[tid*2] = *(const float2*)&vw[tid*2];
  __syncthreads();

  // u = aU @ h + aUb  (2 rows per thread, fp32 from L2)
  #pragma unroll
  for (int jj=0;jj<2;jj++){
    int j = tid + jj*256;
    const ulonglong2* wr = (const ulonglong2*)(aU + (size_t)j*HH);
    u64 a0=0,a1=0,a2=0,a3=0;
    #pragma unroll 4
    for (int i=0;i<128;i+=2){
      ulonglong2 w0 = wr[i], w1 = wr[i+1];
      ulonglong2 h0 = *(const ulonglong2*)&hs[i*4];
      ulonglong2 h1v = *(const ulonglong2*)&hs[i*4+4];
      FMA2(a0,w0.x,h0.x); FMA2(a1,w0.y,h0.y);
      FMA2(a2,w1.x,h1v.x); FMA2(a3,w1.y,h1v.y);
    }
    float2 p0=UNPK(a0), p1=UNPK(a1), p2=UNPK(a2), p3=UNPK(a3);
    us[j] = aUb[j] + (((p0.x+p0.y)+(p1.x+p1.y)) + ((p2.x+p2.y)+(p3.x+p3.y)));
  }
  __syncthreads();

  // scores: 2 threads per l, each 256 h of bf16 Ws
  {
    int l = tid >> 1, half = tid & 1;
    const uint4* wp = (const uint4*)(Wsh + ((size_t)(b*NL + l))*HH + half*256);
    float s = 0.f;
    #pragma unroll 4
    for (int i=0;i<32;i++){
      uint4 q = wp[i];
      const __nv_bfloat162* h2 = (const __nv_bfloat162*)&q;
      int off = half*256 + i*8;
      float4 u0 = *(const float4*)&us[off];
      float4 u1 = *(const float4*)&us[off+4];
      float4 v0 = *(const float4*)&vs[off];
      float4 v1 = *(const float4*)&vs[off+4];
      float2 w0=__bfloat1622float2(h2[0]), w1=__bfloat1622float2(h2[1]);
      float2 w2=__bfloat1622float2(h2[2]), w3=__bfloat1622float2(h2[3]);
      s += fmaxf(w0.x+u0.x,0.f)*v0.x + fmaxf(w0.y+u0.y,0.f)*v0.y
         + fmaxf(w1.x+u0.z,0.f)*v0.z + fmaxf(w1.y+u0.w,0.f)*v0.w
         + fmaxf(w2.x+u1.x,0.f)*v1.x + fmaxf(w2.y+u1.y,0.f)*v1.y
         + fmaxf(w3.x+u1.z,0.f)*v1.z + fmaxf(w3.y+u1.w,0.f)*v1.w;
    }
    s += __shfl_xor_sync(0xffffffffu, s, 1);
    if (!half) sc[l] = s + vb[0];
  }
  __syncthreads();
  // softmax over 128 (warp 0)
  if (tid < 32){
    float m = -1e30f;
    for (int l = tid; l < NL; l += 32) m = fmaxf(m, sc[l]);
    #pragma unroll
    for (int o=16;o;o>>=1) m = fmaxf(m, __shfl_xor_sync(0xffffffffu,m,o));
    float s = 0.f;
    for (int l = tid; l < NL; l += 32){ float e = expf(sc[l]-m); sc[l] = e; s += e; }
    #pragma unroll
    for (int o=16;o;o>>=1) s += __shfl_xor_sync(0xffffffffu,s,o);
    float inv = 1.f/s;
    for (int l = tid; l < NL; l += 32) sc[l] *= inv;
  }
  __syncthreads();
  // ctx: thread owns channels c and c+256 (no shuffles, 16 independent loads each)
  #pragma unroll
  for (int cc=0;cc<2;cc++){
    int c = tid + cc*256;
    const uint4* ep = (const uint4*)(ench + ((size_t)b*CC + c)*NL);
    float s = 0.f;
    #pragma unroll 4
    for (int i=0;i<16;i++){
      uint4 q = ep[i];
      const __nv_bfloat162* h2 = (const __nv_bfloat162*)&q;
      float4 a0 = *(const float4*)&sc[i*8];
      float4 a1 = *(const float4*)&sc[i*8+4];
      float2 e0=__bfloat1622float2(h2[0]), e1=__bfloat1622float2(h2[1]);
      float2 e2=__bfloat1622float2(h2[2]), e3=__bfloat1622float2(h2[3]);
      s += e0.x*a0.x + e0.y*a0.y + e1.x*a0.z + e1.y*a0.w
         + e2.x*a1.x + e2.y*a1.y + e3.x*a1.z + e3.y*a1.w;
    }
    cx[c] = s;
  }
  __syncthreads();
  // y = relu(fcw @ [ctx, h] + fcb)  (2 rows per thread)
  #pragma unroll
  for (int jj=0;jj<2;jj++){
    int j = tid + jj*256;
    const ulonglong2* wr = (const ulonglong2*)(fcw + (size_t)j*(CC+HH));
    u64 a0=0,a1=0,a2=0,a3=0;
    #pragma unroll 4
    for (int i=0;i<128;i+=2){
      ulonglong2 w0 = wr[i], w1 = wr[i+1];
      ulonglong2 c0 = *(const ulonglong2*)&cx[i*4];
      ulonglong2 c1 = *(const ulonglong2*)&cx[i*4+4];
      FMA2(a0,w0.x,c0.x); FMA2(a1,w0.y,c0.y);
      FMA2(a2,w1.x,c1.x); FMA2(a3,w1.y,c1.y);
    }
    #pragma unroll 4
    for (int i=0;i<128;i+=2){
      ulonglong2 w0 = wr[128+i], w1 = wr[128+i+1];
      ulonglong2 h0 = *(const ulonglong2*)&hs[i*4];
      ulonglong2 h1v = *(const ulonglong2*)&hs[i*4+4];
      FMA2(a0,w0.x,h0.x); FMA2(a1,w0.y,h0.y);
      FMA2(a2,w1.x,h1v.x); FMA2(a3,w1.y,h1v.y);
    }
    float2 p0=UNPK(a0), p1=UNPK(a1), p2=UNPK(a2), p3=UNPK(a3);
    float y = (((p0.x+p0.y)+(p1.x+p1.y)) + ((p2.x+p2.y)+(p3.x+p3.y))) + fcb[j];
    yout[(size_t)b*HH + j] = fmaxf(y, 0.f);
  }
}

// ---------------- logits + per-token masked NLL ----------------
__global__ void __launch_bounds__(128) k_logits(const float* __restrict__ ys,
                                                const float* __restrict__ clsw,
                                                const float* __restrict__ clsb,
                                                const int* __restrict__ seq,
                                                float* __restrict__ nll,
                                                float* __restrict__ msk){
  __shared__ float yb[HH];
  __shared__ float lg[VV];
  int t = blockIdx.x >> 8;
  int b = blockIdx.x & 255;
  int tid = threadIdx.x;
  for (int i = tid; i < HH; i += 128)
    yb[i] = ys[((size_t)t*BB + b)*HH + i];
  __syncthreads();
  {
    int v = tid >> 1, half = tid & 1;
    const float4* wr = (const float4*)(clsw + (size_t)v*HH + half*256);
    const float4* yr = (const float4*)(yb + half*256);
    float s = 0.f;
    #pragma unroll 8
    for (int i = 0; i < 64; i++){
      float4 w = wr[i], y = yr[i];
      s += w.x*y.x + w.y*y.y + w.z*y.z + w.w*y.w;
    }
    s += __shfl_xor_sync(0xffffffffu, s, 1);
    if (!half) lg[v] = s + clsb[v];
  }
  __syncthreads();
  if (tid == 0){
    float m = lg[0];
    #pragma unroll
    for (int v = 1; v < VV; v++) m = fmaxf(m, lg[v]);
    float se = 0.f;
    #pragma unroll
    for (int v = 0; v < VV; v++) se += expf(lg[v]-m);
    int label = seq[b*LSEQ + t + 1];
    float lp = lg[label] - m - logf(se);
    bool mk = label > 0;
    nll[blockIdx.x] = mk ? -lp : 0.f;
    msk[blockIdx.x] = mk ? 1.f : 0.f;
  }
}

// ---------------- deterministic final reduction ----------------
__global__ void __launch_bounds__(256) k_reduce(const float* __restrict__ nll,
                                                const float* __restrict__ msk,
                                                float* __restrict__ out){
  __shared__ float sn[256], sm[256];
  int tid = threadIdx.x;
  float a = 0.f, c = 0.f;
  for (int i = tid; i < TT*BB; i += 256){ a += nll[i]; c += msk[i]; }
  sn[tid] = a; sm[tid] = c;
  __syncthreads();
  for (int o = 128; o; o >>= 1){
    if (tid < o){ sn[tid] += sn[tid+o]; sm[tid] += sm[tid+o]; }
    __syncthreads();
  }
  if (tid == 0) out[0] = sn[0] / sm[0];
}

// ---------------- host orchestration ----------------
extern "C" void kernel_launch(void* const* d_in, const int* in_sizes, int n_in,
                              void* d_out, int out_size){
  (void)in_sizes; (void)n_in; (void)out_size;
  const float* enc   = (const float*)d_in[0];
  const int*   seq   = (const int*)  d_in[1];
  const float* emb   = (const float*)d_in[3];
  const float* inis  = (const float*)d_in[4];
  const float* aWw   = (const float*)d_in[5];
  const float* aWb   = (const float*)d_in[6];
  const float* aUw   = (const float*)d_in[7];
  const float* aUb   = (const float*)d_in[8];
  const float* avw   = (const float*)d_in[9];
  const float* avb   = (const float*)d_in[10];
  const float* fcw   = (const float*)d_in[11];
  const float* fcb   = (const float*)d_in[12];
  const float* clsw  = (const float*)d_in[13];
  const float* clsb  = (const float*)d_in[14];
  const float* g0wih = (const float*)d_in[15];
  const float* g0whh = (const float*)d_in[16];
  const float* g0bih = (const float*)d_in[17];
  const float* g0bhh = (const float*)d_in[18];
  const float* g1wih = (const float*)d_in[19];
  const float* g1whh = (const float*)d_in[20];
  const float* g1bih = (const float*)d_in[21];
  const float* g1bhh = (const float*)d_in[22];

  __nv_bfloat16 *Wsh, *ench;
  float *xg, *xs, *ys, *y0, *h0b, *h1b, *gates, *gatesH, *nll, *msk;
  cudaGetSymbolAddress((void**)&Wsh,   g_Wsh);
  cudaGetSymbolAddress((void**)&ench,  g_ench);
  cudaGetSymbolAddress((void**)&xg,    g_xg);
  cudaGetSymbolAddress((void**)&xs,    g_xs);
  cudaGetSymbolAddress((void**)&ys,    g_ys);
  cudaGetSymbolAddress((void**)&y0,    g_y0);
  cudaGetSymbolAddress((void**)&h0b,   g_h0buf);
  cudaGetSymbolAddress((void**)&h1b,   g_h1buf);
  cudaGetSymbolAddress((void**)&gates, g_gates);
  cudaGetSymbolAddress((void**)&gatesH,g_gatesH);
  cudaGetSymbolAddress((void**)&nll,   g_nll);
  cudaGetSymbolAddress((void**)&msk,   g_msk);

  // one-time precompute (all parallel)
  k_inith<<<(BH+255)/256, 256>>>(inis, h0b, h1b);
  k_embed<<<(TT*BH+255)/256, 256>>>(emb, seq, xs);
  k_tobf16<<<(BB*CC*NL/4+255)/256, 256>>>(enc, ench, BB*CC*NL/4);
  k_ws<<<dim3(512, 8), 256>>>(enc, aWw, aWb, Wsh);
  k_mm1<<<dim3(92, 24), 256>>>(xs, g0wih, 1024, 512, xg, 3*HH);

  // y0
  k_attnfc<<<BB, 256>>>(Wsh, ench, h1b, aUw, aUb, avw, avb, fcw, fcb, y0);

  const float* yprev = y0;
  for (int t = 0; t < TT; t++){
    float* h0r = h0b + (size_t)(t & 1)*BH;
    float* h0w = h0b + (size_t)((t+1) & 1)*BH;
    float* h1r = h1b + (size_t)(t & 1)*BH;
    float* h1w = h1b + (size_t)((t+1) & 1)*BH;
    // GRU0: phase0 A=y_prev vs wih[:, :512] (stride 1024); phase1 A=h0prev vs whh
    k_gates<<<dim3(4,24), 256>>>(yprev, h0r, g0wih, 1024, g0whh, gates, gatesH);
    k_pw<<<512, 256>>>(gates, gatesH, xg + (size_t)t*BB*3*HH, h0r, g0bih, g0bhh, h0w);
    // GRU1: phase0 A=h0new vs wih (stride 512); phase1 A=h1prev vs whh
    k_gates<<<dim3(4,24), 256>>>(h0w, h1r, g1wih, 512, g1whh, gates, gatesH);
    k_pw<<<512, 256>>>(gates, gatesH, (const float*)nullptr, h1r, g1bih, g1bhh, h1w);
    // attention + fc
    k_attnfc<<<BB, 256>>>(Wsh, ench, h1w, aUw, aUb, avw, avb, fcw, fcb,
                          ys + (size_t)t*BH);
    yprev = ys + (size_t)t*BH;
  }

  k_logits<<<TT*BB, 128>>>(ys, clsw, clsb, seq, nll, msk);
  k_reduce<<<1, 256>>>(nll, msk, (float*)d_out);
}

// round 4
// speedup vs baseline: 2.5253x; 2.4137x over previous
#include <cuda_runtime.h>
#include <cuda_bf16.h>
#include <math.h>

#define BB 256
#define HH 512
#define CC 512
#define NL 128
#define TT 23
#define LSEQ 24
#define VV 64
#define BH (BB*HH)
#define NTOK (TT*BB)

typedef unsigned long long u64;

__device__ __forceinline__ void FMA2(u64 &d, u64 a, u64 b){
  asm("fma.rn.f32x2 %0, %1, %2, %0;" : "+l"(d) : "l"(a), "l"(b));
}
__device__ __forceinline__ u64 PACK2(float x, float y){
  u64 r; asm("mov.b64 %0, {%1, %2};" : "=l"(r) : "f"(x), "f"(y)); return r;
}
__device__ __forceinline__ float2 UNPK(u64 v){
  float2 r; asm("mov.b64 {%0, %1}, %2;" : "=f"(r.x), "=f"(r.y) : "l"(v)); return r;
}

// ---------------- static scratch ----------------
__device__ __nv_bfloat16 g_Wsh[(size_t)BB*NL*HH];
__device__ __nv_bfloat16 g_ench[(size_t)BB*CC*NL];
__device__ float g_xg[(size_t)TT*BB*3*HH];
__device__ float g_xs[(size_t)TT*BH];
__device__ float g_ys[(size_t)TT*BH];
__device__ float g_y0[BH];
__device__ float g_h0buf[2][BH];
__device__ float g_h1buf[2][BH];
__device__ float g_gp[4][(size_t)BB*3*HH];   // gate GEMM partials (4 z-slices)
__device__ float g_fp[4][BH];                // fc partials
__device__ float g_Up[2][BH];                // Uh partials
__device__ float g_ctx[BH];
__device__ float g_lg[2][(size_t)NTOK*VV];   // logits partials
__device__ float g_nll[NTOK];
__device__ float g_msk[NTOK];

// ---------------- init hidden states ----------------
__global__ void k_inith(const float* __restrict__ init_state,
                        float* __restrict__ h0, float* __restrict__ h1){
  int idx = blockIdx.x*blockDim.x + threadIdx.x;
  if (idx < BH){
    int j = idx & (HH-1);
    h0[idx] = init_state[j];
    h1[idx] = init_state[HH + j];
  }
}

// ---------------- embedding gather ----------------
__global__ void k_embed(const float* __restrict__ emb, const int* __restrict__ seq,
                        float* __restrict__ xs){
  int idx = blockIdx.x*blockDim.x + threadIdx.x;
  if (idx < TT*BH){
    int h = idx & (HH-1);
    int r = idx >> 9;
    int b = r & (BB-1);
    int t = r >> 8;
    int tok = seq[b*LSEQ + t];
    xs[idx] = emb[(size_t)tok*HH + h];
  }
}

// ---------------- fp32 -> bf16 copy ----------------
__global__ void k_tobf16(const float* __restrict__ in, __nv_bfloat16* __restrict__ out, int n4){
  int idx = blockIdx.x*blockDim.x + threadIdx.x;
  if (idx < n4){
    float4 v = *(const float4*)&in[(size_t)idx*4];
    *(__nv_bfloat162*)&out[(size_t)idx*4]   = __floats2bfloat162_rn(v.x, v.y);
    *(__nv_bfloat162*)&out[(size_t)idx*4+2] = __floats2bfloat162_rn(v.z, v.w);
  }
}

// ---------------- Ws GEMM -> bf16 out. M=32768, N=512, K=512 ----------------
__global__ void __launch_bounds__(256) k_ws(const float* __restrict__ enc,
                                            const float* __restrict__ Ww,
                                            const float* __restrict__ Wb,
                                            __nv_bfloat16* __restrict__ Wsh){
  __shared__ __align__(16) float At[2][16][68];
  __shared__ __align__(16) float Wt[2][16][68];
  int m0 = blockIdx.x*64, n0 = blockIdx.y*64;
  int bb_ = m0 >> 7, l0 = m0 & 127;
  int tid = threadIdx.x, tm = tid & 15, tn = tid >> 4;
  u64 acc[4][2] = {};
  float4 raA, raW;
  int akk = tid >> 4, al4 = (tid & 15)*4;
  int wnn = tid >> 2, wk4 = (tid & 3)*4;

  auto loadT = [&](int t){
    int kc = t*16;
    raA = *(const float4*)&enc[(size_t)bb_*CC*NL + (size_t)(kc + akk)*NL + l0 + al4];
    raW = *(const float4*)&Ww[(size_t)(n0 + wnn)*CC + kc + wk4];
  };
  auto storeT = [&](int buf){
    *(float4*)&At[buf][akk][al4] = raA;
    Wt[buf][wk4+0][wnn]=raW.x; Wt[buf][wk4+1][wnn]=raW.y;
    Wt[buf][wk4+2][wnn]=raW.z; Wt[buf][wk4+3][wnn]=raW.w;
  };

  loadT(0); storeT(0); __syncthreads();
  for (int t=0;t<32;t++){
    int buf = t & 1;
    if (t+1 < 32) loadT(t+1);
    #pragma unroll
    for (int kk=0;kk<16;kk++){
      float4 av = *(const float4*)&At[buf][kk][tm*4];
      ulonglong2 wv = *(const ulonglong2*)&Wt[buf][kk][tn*4];
      u64 a0=PACK2(av.x,av.x), a1=PACK2(av.y,av.y), a2=PACK2(av.z,av.z), a3=PACK2(av.w,av.w);
      FMA2(acc[0][0],a0,wv.x); FMA2(acc[0][1],a0,wv.y);
      FMA2(acc[1][0],a1,wv.x); FMA2(acc[1][1],a1,wv.y);
      FMA2(acc[2][0],a2,wv.x); FMA2(acc[2][1],a2,wv.y);
      FMA2(acc[3][0],a3,wv.x); FMA2(acc[3][1],a3,wv.y);
    }
    if (t+1 < 32) storeT((t+1)&1);
    __syncthreads();
  }
  #pragma unroll
  for (int mi=0;mi<4;mi++){
    int m = m0 + tm*4 + mi;
    #pragma unroll
    for (int h=0;h<2;h++){
      float2 p = UNPK(acc[mi][h]);
      int n = n0 + tn*4 + h*2;
      *(__nv_bfloat162*)&Wsh[(size_t)m*HH + n] =
          __floats2bfloat162_rn(p.x + Wb[n], p.y + Wb[n+1]);
    }
  }
}

// ---------------- xg precompute GEMM: C = A[M,512] @ W(stride,off)^T ----------
__global__ void __launch_bounds__(256) k_mm1(const float* __restrict__ A,
                                             const float* __restrict__ W,
                                             int ws, int wOff,
                                             float* __restrict__ C, int ldc){
  __shared__ __align__(16) float At[2][16][68];
  __shared__ __align__(16) float Wt[2][16][68];
  int m0 = blockIdx.x*64, n0 = blockIdx.y*64;
  int tid = threadIdx.x, tm = tid & 15, tn = tid >> 4;
  u64 acc[4][2] = {};
  float4 ra, rw;
  int mm = tid >> 2, k4 = (tid & 3)*4;

  auto loadT = [&](int t){
    int kc = t*16;
    ra = *(const float4*)&A[(size_t)(m0+mm)*512 + kc + k4];
    rw = *(const float4*)&W[(size_t)(n0+mm)*ws + wOff + kc + k4];
  };
  auto storeT = [&](int buf){
    At[buf][k4+0][mm]=ra.x; At[buf][k4+1][mm]=ra.y; At[buf][k4+2][mm]=ra.z; At[buf][k4+3][mm]=ra.w;
    Wt[buf][k4+0][mm]=rw.x; Wt[buf][k4+1][mm]=rw.y; Wt[buf][k4+2][mm]=rw.z; Wt[buf][k4+3][mm]=rw.w;
  };

  loadT(0); storeT(0); __syncthreads();
  for (int t=0;t<32;t++){
    int buf = t & 1;
    if (t+1 < 32) loadT(t+1);
    #pragma unroll
    for (int kk=0;kk<16;kk++){
      float4 av = *(const float4*)&At[buf][kk][tm*4];
      ulonglong2 wv = *(const ulonglong2*)&Wt[buf][kk][tn*4];
      u64 a0=PACK2(av.x,av.x), a1=PACK2(av.y,av.y), a2=PACK2(av.z,av.z), a3=PACK2(av.w,av.w);
      FMA2(acc[0][0],a0,wv.x); FMA2(acc[0][1],a0,wv.y);
      FMA2(acc[1][0],a1,wv.x); FMA2(acc[1][1],a1,wv.y);
      FMA2(acc[2][0],a2,wv.x); FMA2(acc[2][1],a2,wv.y);
      FMA2(acc[3][0],a3,wv.x); FMA2(acc[3][1],a3,wv.y);
    }
    if (t+1 < 32) storeT((t+1)&1);
    __syncthreads();
  }
  #pragma unroll
  for (int mi=0;mi<4;mi++){
    int m = m0 + tm*4 + mi;
    #pragma unroll
    for (int h=0;h<2;h++){
      float2 p = UNPK(acc[mi][h]);
      int n = n0 + tn*4 + h*2;
      *(float2*)&C[(size_t)m*ldc + n] = make_float2(p.x, p.y);
    }
  }
}

// ---------------- generic K-split GEMM: per-z 64x64 tile, K=256 (16 tiles) ----------------
// z = blockIdx.z: set = z>>1 (operand pair), kh = z&1 (K-half). Writes raw partial to Cz[z].
__global__ void __launch_bounds__(256) k_g64(const float* __restrict__ A0, int wA0,
                                             const float* __restrict__ W0, int s0, int o0,
                                             const float* __restrict__ A1, int wA1,
                                             const float* __restrict__ W1, int s1, int o1,
                                             float* __restrict__ C0, float* __restrict__ C1,
                                             float* __restrict__ C2, float* __restrict__ C3,
                                             int ldc){
  __shared__ __align__(16) float At[2][16][68];
  __shared__ __align__(16) float Wt[2][16][68];
  int z = blockIdx.z;
  int set = z >> 1, kbase = (z & 1)*256;
  const float* A = set ? A1 : A0;
  const float* W = set ? W1 : W0;
  int wA = set ? wA1 : wA0;
  int s  = set ? s1 : s0;
  int o  = set ? o1 : o0;
  float* C = (z==0) ? C0 : (z==1) ? C1 : (z==2) ? C2 : C3;

  int m0 = blockIdx.x*64, n0 = blockIdx.y*64;
  int tid = threadIdx.x, tm = tid & 15, tn = tid >> 4;
  u64 acc[4][2] = {};
  float4 ra, rw;
  int mm = tid >> 2, k4 = (tid & 3)*4;

  auto loadT = [&](int t){
    int kc = kbase + t*16;
    ra = *(const float4*)&A[(size_t)(m0+mm)*wA + kc + k4];
    rw = *(const float4*)&W[(size_t)(n0+mm)*s + o + kc + k4];
  };
  auto storeT = [&](int buf){
    At[buf][k4+0][mm]=ra.x; At[buf][k4+1][mm]=ra.y; At[buf][k4+2][mm]=ra.z; At[buf][k4+3][mm]=ra.w;
    Wt[buf][k4+0][mm]=rw.x; Wt[buf][k4+1][mm]=rw.y; Wt[buf][k4+2][mm]=rw.z; Wt[buf][k4+3][mm]=rw.w;
  };

  loadT(0); storeT(0); __syncthreads();
  for (int t=0;t<16;t++){
    int buf = t & 1;
    if (t+1 < 16) loadT(t+1);
    #pragma unroll
    for (int kk=0;kk<16;kk++){
      float4 av = *(const float4*)&At[buf][kk][tm*4];
      ulonglong2 wv = *(const ulonglong2*)&Wt[buf][kk][tn*4];
      u64 a0=PACK2(av.x,av.x), a1=PACK2(av.y,av.y), a2=PACK2(av.z,av.z), a3=PACK2(av.w,av.w);
      FMA2(acc[0][0],a0,wv.x); FMA2(acc[0][1],a0,wv.y);
      FMA2(acc[1][0],a1,wv.x); FMA2(acc[1][1],a1,wv.y);
      FMA2(acc[2][0],a2,wv.x); FMA2(acc[2][1],a2,wv.y);
      FMA2(acc[3][0],a3,wv.x); FMA2(acc[3][1],a3,wv.y);
    }
    if (t+1 < 16) storeT((t+1)&1);
    __syncthreads();
  }
  #pragma unroll
  for (int mi=0;mi<4;mi++){
    int m = m0 + tm*4 + mi;
    #pragma unroll
    for (int h=0;h<2;h++){
      float2 p = UNPK(acc[mi][h]);
      int n = n0 + tn*4 + h*2;
      *(float2*)&C[(size_t)m*ldc + n] = make_float2(p.x, p.y);
    }
  }
}

// ---------------- GRU pointwise: combine 4 gate partials ----------------
__global__ void __launch_bounds__(256) k_pw(const float* __restrict__ P0,
                                            const float* __restrict__ P1,
                                            const float* __restrict__ P2,
                                            const float* __restrict__ P3,
                                            const float* __restrict__ xg,
                                            const float* __restrict__ hprev,
                                            const float* __restrict__ bih,
                                            const float* __restrict__ bhh,
                                            float* __restrict__ hnew){
  int idx = blockIdx.x*256 + threadIdx.x;   // < BH
  int b = idx >> 9, j = idx & (HH-1);
  size_t r0 = (size_t)b*(3*HH);
  float gr = P0[r0+j] + P1[r0+j] + P2[r0+j] + P3[r0+j] + bih[j] + bhh[j];
  float gz = P0[r0+HH+j] + P1[r0+HH+j] + P2[r0+HH+j] + P3[r0+HH+j] + bih[HH+j] + bhh[HH+j];
  float gi = P0[r0+2*HH+j] + P1[r0+2*HH+j] + bih[2*HH+j];
  float gh = P2[r0+2*HH+j] + P3[r0+2*HH+j] + bhh[2*HH+j];
  if (xg){
    gr += xg[r0+j]; gz += xg[r0+HH+j]; gi += xg[r0+2*HH+j];
  }
  float r = 1.f/(1.f+expf(-gr));
  float z = 1.f/(1.f+expf(-gz));
  float n = tanhf(gi + r*gh);
  hnew[idx] = (1.f-z)*n + z*hprev[idx];
}

// ---------------- fc pointwise: y = relu(sum partials + b) ----------------
__global__ void __launch_bounds__(256) k_pwfc(const float* __restrict__ F0,
                                              const float* __restrict__ F1,
                                              const float* __restrict__ F2,
                                              const float* __restrict__ F3,
                                              const float* __restrict__ fcb,
                                              float* __restrict__ y){
  int idx = blockIdx.x*256 + threadIdx.x;   // < BH
  int j = idx & (HH-1);
  float v = F0[idx] + F1[idx] + F2[idx] + F3[idx] + fcb[j];
  y[idx] = fmaxf(v, 0.f);
}

// ---------------- attention: scores + softmax + ctx (bf16 streams) ----------------
__global__ void __launch_bounds__(256) k_attn(const __nv_bfloat16* __restrict__ Wsh,
                                              const __nv_bfloat16* __restrict__ ench,
                                              const float* __restrict__ UhA,
                                              const float* __restrict__ UhB,
                                              const float* __restrict__ aUb,
                                              const float* __restrict__ vw,
                                              const float* __restrict__ vb,
                                              float* __restrict__ ctx){
  __shared__ __align__(16) float us[HH];
  __shared__ __align__(16) float vs[HH];
  __shared__ __align__(16) float sc[NL];
  int b = blockIdx.x, tid = threadIdx.x;

  {
    float2 a = *(const float2*)&UhA[(size_t)b*HH + tid*2];
    float2 c = *(const float2*)&UhB[(size_t)b*HH + tid*2];
    float2 u = *(const float2*)&aUb[tid*2];
    us[tid*2]   = a.x + c.x + u.x;
    us[tid*2+1] = a.y + c.y + u.y;
    *(float2*)&vs[tid*2] = *(const float2*)&vw[tid*2];
  }
  __syncthreads();

  // scores: 2 threads per l, each 256 h
  {
    int l = tid >> 1, half = tid & 1;
    const uint4* wp = (const uint4*)(Wsh + ((size_t)(b*NL + l))*HH + half*256);
    float s = 0.f;
    #pragma unroll 4
    for (int i=0;i<32;i++){
      uint4 q = wp[i];
      const __nv_bfloat162* h2 = (const __nv_bfloat162*)&q;
      int off = half*256 + i*8;
      float4 u0 = *(const float4*)&us[off];
      float4 u1 = *(const float4*)&us[off+4];
      float4 v0 = *(const float4*)&vs[off];
      float4 v1 = *(const float4*)&vs[off+4];
      float2 w0=__bfloat1622float2(h2[0]), w1=__bfloat1622float2(h2[1]);
      float2 w2=__bfloat1622float2(h2[2]), w3=__bfloat1622float2(h2[3]);
      s += fmaxf(w0.x+u0.x,0.f)*v0.x + fmaxf(w0.y+u0.y,0.f)*v0.y
         + fmaxf(w1.x+u0.z,0.f)*v0.z + fmaxf(w1.y+u0.w,0.f)*v0.w
         + fmaxf(w2.x+u1.x,0.f)*v1.x + fmaxf(w2.y+u1.y,0.f)*v1.y
         + fmaxf(w3.x+u1.z,0.f)*v1.z + fmaxf(w3.y+u1.w,0.f)*v1.w;
    }
    s += __shfl_xor_sync(0xffffffffu, s, 1);
    if (!half) sc[l] = s + vb[0];
  }
  __syncthreads();
  if (tid < 32){
    float m = -1e30f;
    for (int l = tid; l < NL; l += 32) m = fmaxf(m, sc[l]);
    #pragma unroll
    for (int o=16;o;o>>=1) m = fmaxf(m, __shfl_xor_sync(0xffffffffu,m,o));
    float s = 0.f;
    for (int l = tid; l < NL; l += 32){ float e = expf(sc[l]-m); sc[l] = e; s += e; }
    #pragma unroll
    for (int o=16;o;o>>=1) s += __shfl_xor_sync(0xffffffffu,s,o);
    float inv = 1.f/s;
    for (int l = tid; l < NL; l += 32) sc[l] *= inv;
  }
  __syncthreads();
  // ctx: thread owns channels c and c+256
  #pragma unroll
  for (int cc=0;cc<2;cc++){
    int c = tid + cc*256;
    const uint4* ep = (const uint4*)(ench + ((size_t)b*CC + c)*NL);
    float s = 0.f;
    #pragma unroll 4
    for (int i=0;i<16;i++){
      uint4 q = ep[i];
      const __nv_bfloat162* h2 = (const __nv_bfloat162*)&q;
      float4 a0 = *(const float4*)&sc[i*8];
      float4 a1 = *(const float4*)&sc[i*8+4];
      float2 e0=__bfloat1622float2(h2[0]), e1=__bfloat1622float2(h2[1]);
      float2 e2=__bfloat1622float2(h2[2]), e3=__bfloat1622float2(h2[3]);
      s += e0.x*a0.x + e0.y*a0.y + e1.x*a0.z + e1.y*a0.w
         + e2.x*a1.x + e2.y*a1.y + e3.x*a1.z + e3.y*a1.w;
    }
    ctx[(size_t)b*CC + c] = s;
  }
}

// ---------------- per-token NLL from logits partials ----------------
__global__ void __launch_bounds__(256) k_nll(const float* __restrict__ LA,
                                             const float* __restrict__ LB,
                                             const float* __restrict__ clsb,
                                             const int* __restrict__ seq,
                                             float* __restrict__ nll,
                                             float* __restrict__ msk){
  int idx = blockIdx.x*256 + threadIdx.x;   // < NTOK
  int t = idx >> 8, b = idx & 255;
  float lg[VV];
  const float4* pa = (const float4*)(LA + (size_t)idx*VV);
  const float4* pb = (const float4*)(LB + (size_t)idx*VV);
  float m = -1e30f;
  #pragma unroll
  for (int i=0;i<16;i++){
    float4 a = pa[i], c = pb[i];
    float4 d = *(const float4*)&clsb[i*4];
    lg[i*4+0] = a.x + c.x + d.x;
    lg[i*4+1] = a.y + c.y + d.y;
    lg[i*4+2] = a.z + c.z + d.z;
    lg[i*4+3] = a.w + c.w + d.w;
  }
  #pragma unroll
  for (int v=0;v<VV;v++) m = fmaxf(m, lg[v]);
  float se = 0.f;
  #pragma unroll
  for (int v=0;v<VV;v++) se += expf(lg[v]-m);
  int label = seq[b*LSEQ + t + 1];
  float lp = lg[label] - m - logf(se);
  bool mk = label > 0;
  nll[idx] = mk ? -lp : 0.f;
  msk[idx] = mk ? 1.f : 0.f;
}

// ---------------- deterministic final reduction ----------------
__global__ void __launch_bounds__(256) k_reduce(const float* __restrict__ nll,
                                                const float* __restrict__ msk,
                                                float* __restrict__ out){
  __shared__ float sn[256], sm[256];
  int tid = threadIdx.x;
  float a = 0.f, c = 0.f;
  for (int i = tid; i < NTOK; i += 256){ a += nll[i]; c += msk[i]; }
  sn[tid] = a; sm[tid] = c;
  __syncthreads();
  for (int o = 128; o; o >>= 1){
    if (tid < o){ sn[tid] += sn[tid+o]; sm[tid] += sm[tid+o]; }
    __syncthreads();
  }
  if (tid == 0) out[0] = sn[0] / sm[0];
}

// ---------------- host orchestration ----------------
extern "C" void kernel_launch(void* const* d_in, const int* in_sizes, int n_in,
                              void* d_out, int out_size){
  (void)in_sizes; (void)n_in; (void)out_size;
  const float* enc   = (const float*)d_in[0];
  const int*   seq   = (const int*)  d_in[1];
  const float* emb   = (const float*)d_in[3];
  const float* inis  = (const float*)d_in[4];
  const float* aWw   = (const float*)d_in[5];
  const float* aWb   = (const float*)d_in[6];
  const float* aUw   = (const float*)d_in[7];
  const float* aUb   = (const float*)d_in[8];
  const float* avw   = (const float*)d_in[9];
  const float* avb   = (const float*)d_in[10];
  const float* fcw   = (const float*)d_in[11];
  const float* fcb   = (const float*)d_in[12];
  const float* clsw  = (const float*)d_in[13];
  const float* clsb  = (const float*)d_in[14];
  const float* g0wih = (const float*)d_in[15];
  const float* g0whh = (const float*)d_in[16];
  const float* g0bih = (const float*)d_in[17];
  const float* g0bhh = (const float*)d_in[18];
  const float* g1wih = (const float*)d_in[19];
  const float* g1whh = (const float*)d_in[20];
  const float* g1bih = (const float*)d_in[21];
  const float* g1bhh = (const float*)d_in[22];

  __nv_bfloat16 *Wsh, *ench;
  float *xg, *xs, *ys, *y0, *h0b, *h1b, *gp, *fp, *Up, *ctx, *lg, *nll, *msk;
  cudaGetSymbolAddress((void**)&Wsh,  g_Wsh);
  cudaGetSymbolAddress((void**)&ench, g_ench);
  cudaGetSymbolAddress((void**)&xg,   g_xg);
  cudaGetSymbolAddress((void**)&xs,   g_xs);
  cudaGetSymbolAddress((void**)&ys,   g_ys);
  cudaGetSymbolAddress((void**)&y0,   g_y0);
  cudaGetSymbolAddress((void**)&h0b,  g_h0buf);
  cudaGetSymbolAddress((void**)&h1b,  g_h1buf);
  cudaGetSymbolAddress((void**)&gp,   g_gp);
  cudaGetSymbolAddress((void**)&fp,   g_fp);
  cudaGetSymbolAddress((void**)&Up,   g_Up);
  cudaGetSymbolAddress((void**)&ctx,  g_ctx);
  cudaGetSymbolAddress((void**)&lg,   g_lg);
  cudaGetSymbolAddress((void**)&nll,  g_nll);
  cudaGetSymbolAddress((void**)&msk,  g_msk);

  const size_t GSZ = (size_t)BB*3*HH;
  float* GP[4] = {gp, gp+GSZ, gp+2*GSZ, gp+3*GSZ};
  float* FP[4] = {fp, fp+BH, fp+2*BH, fp+3*BH};
  float* UP[2] = {Up, Up+BH};
  float* LG[2] = {lg, lg+(size_t)NTOK*VV};

  // one-time precompute
  k_inith<<<(BH+255)/256, 256>>>(inis, h0b, h1b);
  k_embed<<<(TT*BH+255)/256, 256>>>(emb, seq, xs);
  k_tobf16<<<(BB*CC*NL/4+255)/256, 256>>>(enc, ench, BB*CC*NL/4);
  k_ws<<<dim3(512, 8), 256>>>(enc, aWw, aWb, Wsh);
  k_mm1<<<dim3(92, 24), 256>>>(xs, g0wih, 1024, 512, xg, 3*HH);

  auto attn_fc = [&](const float* h1cur, float* yout){
    // Uh = h1 @ aU^T  (2 K-halves)
    k_g64<<<dim3(4,8,2), 256>>>(h1cur, HH, aUw, 512, 0,
                                nullptr, 0, nullptr, 0, 0,
                                UP[0], UP[1], nullptr, nullptr, HH);
    k_attn<<<BB, 256>>>(Wsh, ench, UP[0], UP[1], aUb, avw, avb, ctx);
    // fc: z0/1 = ctx K-halves vs fcw[:, :512]; z2/3 = h K-halves vs fcw[:, 512:]
    k_g64<<<dim3(4,8,4), 256>>>(ctx, CC, fcw, 1024, 0,
                                h1cur, HH, fcw, 1024, 512,
                                FP[0], FP[1], FP[2], FP[3], HH);
    k_pwfc<<<BH/256, 256>>>(FP[0], FP[1], FP[2], FP[3], fcb, yout);
  };

  // y0
  attn_fc(h1b, y0);

  const float* yprev = y0;
  for (int t = 0; t < TT; t++){
    float* h0r = h0b + (size_t)(t & 1)*BH;
    float* h0w = h0b + (size_t)((t+1) & 1)*BH;
    float* h1r = h1b + (size_t)(t & 1)*BH;
    float* h1w = h1b + (size_t)((t+1) & 1)*BH;
    // GRU0 gates: set0 = y_prev @ wih[:, :512], set1 = h0prev @ whh
    k_g64<<<dim3(4,24,4), 256>>>(yprev, HH, g0wih, 1024, 0,
                                 h0r, HH, g0whh, 512, 0,
                                 GP[0], GP[1], GP[2], GP[3], 3*HH);
    k_pw<<<BH/256, 256>>>(GP[0], GP[1], GP[2], GP[3],
                          xg + (size_t)t*GSZ, h0r, g0bih, g0bhh, h0w);
    // GRU1 gates
    k_g64<<<dim3(4,24,4), 256>>>(h0w, HH, g1wih, 512, 0,
                                 h1r, HH, g1whh, 512, 0,
                                 GP[0], GP[1], GP[2], GP[3], 3*HH);
    k_pw<<<BH/256, 256>>>(GP[0], GP[1], GP[2], GP[3],
                          (const float*)nullptr, h1r, g1bih, g1bhh, h1w);
    // attention + out_proj
    attn_fc(h1w, ys + (size_t)t*BH);
    yprev = ys + (size_t)t*BH;
  }

  // logits GEMM (M=5888, N=64, K=512 in 2 halves) + NLL + reduce
  k_g64<<<dim3(92,1,2), 256>>>(ys, HH, clsw, 512, 0,
                               nullptr, 0, nullptr, 0, 0,
                               LG[0], LG[1], nullptr, nullptr, VV);
  k_nll<<<NTOK/256, 256>>>(LG[0], LG[1], clsb, seq, nll, msk);
  k_reduce<<<1, 256>>>(nll, msk, (float*)d_out);
}